// round 1
// baseline (speedup 1.0000x reference)
#include <cuda_runtime.h>
#include <cuda_bf16.h>

// 8x8 blockwise DCT with output transpose:
//   OUT[v][u] = sum_{k,l} D[u,k] * X[k,l] * D[v,l]
// x: (32, 3, 512, 512) fp32   dct_basis: (8,8) fp32
// One thread per 8x8 block. 32*3*64*64 = 393216 blocks.

#define IMG_DIM   512
#define NIMG      (32 * 3)
#define BLK_PER_ROW (IMG_DIM / 8)           // 64
#define NBLOCKS   (NIMG * BLK_PER_ROW * BLK_PER_ROW)  // 393216
#define TPB       256

__global__ __launch_bounds__(TPB) void dct_blocks_kernel(
    const float* __restrict__ x,
    const float* __restrict__ dct,
    float* __restrict__ out)
{
    __shared__ float D[64];
    if (threadIdx.x < 64) D[threadIdx.x] = dct[threadIdx.x];
    __syncthreads();

    int g = blockIdx.x * TPB + threadIdx.x;       // block index, grid sized exactly
    int bx    = g & (BLK_PER_ROW - 1);
    int tmpg  = g >> 6;
    int by    = tmpg & (BLK_PER_ROW - 1);
    int img   = tmpg >> 6;

    size_t base = ((size_t)img * IMG_DIM + (size_t)by * 8) * IMG_DIM + (size_t)bx * 8;
    const float* src = x + base;
    float*       dst = out + base;

    // Stage 1: t[u][l] = sum_k D[u,k] * X[k,l]   (stream X one row at a time)
    float t[8][8];
    #pragma unroll
    for (int u = 0; u < 8; ++u)
        #pragma unroll
        for (int l = 0; l < 8; ++l)
            t[u][l] = 0.0f;

    #pragma unroll
    for (int k = 0; k < 8; ++k) {
        float4 a = *(const float4*)(src + (size_t)k * IMG_DIM);
        float4 b = *(const float4*)(src + (size_t)k * IMG_DIM + 4);
        float xr[8] = {a.x, a.y, a.z, a.w, b.x, b.y, b.z, b.w};
        #pragma unroll
        for (int u = 0; u < 8; ++u) {
            float d = D[u * 8 + k];
            #pragma unroll
            for (int l = 0; l < 8; ++l)
                t[u][l] = fmaf(d, xr[l], t[u][l]);
        }
    }

    // Stage 2: OUT[v][u] = sum_l t[u][l] * D[v,l]   (emit one output row per v)
    #pragma unroll
    for (int v = 0; v < 8; ++v) {
        float o[8];
        #pragma unroll
        for (int u = 0; u < 8; ++u) {
            float s = 0.0f;
            #pragma unroll
            for (int l = 0; l < 8; ++l)
                s = fmaf(t[u][l], D[v * 8 + l], s);
            o[u] = s;
        }
        *(float4*)(dst + (size_t)v * IMG_DIM)     = make_float4(o[0], o[1], o[2], o[3]);
        *(float4*)(dst + (size_t)v * IMG_DIM + 4) = make_float4(o[4], o[5], o[6], o[7]);
    }
}

extern "C" void kernel_launch(void* const* d_in, const int* in_sizes, int n_in,
                              void* d_out, int out_size)
{
    const float* x   = (const float*)d_in[0];
    const float* dct = (const float*)d_in[1];
    float*       out = (float*)d_out;

    dct_blocks_kernel<<<NBLOCKS / TPB, TPB>>>(x, dct, out);
}

// round 2
// speedup vs baseline: 1.1654x; 1.1654x over previous
#include <cuda_runtime.h>
#include <cuda_bf16.h>

// 8x8 blockwise DCT with output transpose:
//   OUT[v][u] = sum_{k,l} D[u,k] * X[k,l] * D[v,l]
// x: (32, 3, 512, 512) fp32   dct_basis: (8,8) fp32
// TWO threads per 8x8 block: thread half h owns output columns u in [4h, 4h+4).
// Cuts per-thread accumulator state from 64 -> 32 regs so 4 CTAs/SM fit
// (64-reg cap), raising occupancy 20% -> ~50% to hide DRAM latency.

#define IMG_DIM     512
#define NIMG        (32 * 3)
#define BLK_PER_ROW (IMG_DIM / 8)                                 // 64
#define NBLOCKS     (NIMG * BLK_PER_ROW * BLK_PER_ROW)            // 393216
#define NTHREADS    (NBLOCKS * 2)                                 // 786432
#define TPB         256

__global__ __launch_bounds__(TPB, 4) void dct_blocks_kernel(
    const float* __restrict__ x,
    const float* __restrict__ dct,
    float* __restrict__ out)
{
    __shared__ float Ds[64];   // D row-major: Ds[v*8+l] = D[v][l]
    __shared__ float Dt[64];   // D transposed: Dt[k*8+u] = D[u][k]
    if (threadIdx.x < 64) {
        float val = dct[threadIdx.x];
        Ds[threadIdx.x] = val;
        int u = threadIdx.x >> 3;
        int k = threadIdx.x & 7;
        Dt[k * 8 + u] = val;
    }
    __syncthreads();

    int g    = blockIdx.x * TPB + threadIdx.x;  // 0 .. NTHREADS-1
    int half = g & 1;                           // which 4 output columns
    int p    = g >> 1;                          // block index
    int bx   = p & (BLK_PER_ROW - 1);
    int tmp  = p >> 6;
    int by   = tmp & (BLK_PER_ROW - 1);
    int img  = tmp >> 6;
    int uo   = half * 4;

    size_t base = ((size_t)img * IMG_DIM + (size_t)by * 8) * IMG_DIM + (size_t)bx * 8;
    const float* src = x + base;
    float*       dst = out + base;

    // Stage 1: t[u4][l] = sum_k D[uo+u4, k] * X[k, l]   (stream X rows)
    float t[4][8];
    #pragma unroll
    for (int u4 = 0; u4 < 4; ++u4)
        #pragma unroll
        for (int l = 0; l < 8; ++l)
            t[u4][l] = 0.0f;

    #pragma unroll
    for (int k = 0; k < 8; ++k) {
        float4 a = *(const float4*)(src + (size_t)k * IMG_DIM);
        float4 b = *(const float4*)(src + (size_t)k * IMG_DIM + 4);
        float xr[8] = {a.x, a.y, a.z, a.w, b.x, b.y, b.z, b.w};
        float4 dk = *(const float4*)(Dt + k * 8 + uo);  // D[uo..uo+3][k]
        float du[4] = {dk.x, dk.y, dk.z, dk.w};
        #pragma unroll
        for (int u4 = 0; u4 < 4; ++u4)
            #pragma unroll
            for (int l = 0; l < 8; ++l)
                t[u4][l] = fmaf(du[u4], xr[l], t[u4][l]);
    }

    // Stage 2: OUT[v][uo+u4] = sum_l t[u4][l] * D[v, l]; emit per output row v.
    #pragma unroll
    for (int v = 0; v < 8; ++v) {
        float4 d0 = *(const float4*)(Ds + v * 8);
        float4 d1 = *(const float4*)(Ds + v * 8 + 4);
        float dv[8] = {d0.x, d0.y, d0.z, d0.w, d1.x, d1.y, d1.z, d1.w};
        float o[4];
        #pragma unroll
        for (int u4 = 0; u4 < 4; ++u4) {
            float s = 0.0f;
            #pragma unroll
            for (int l = 0; l < 8; ++l)
                s = fmaf(t[u4][l], dv[l], s);
            o[u4] = s;
        }
        *(float4*)(dst + (size_t)v * IMG_DIM + uo) = make_float4(o[0], o[1], o[2], o[3]);
    }
}

extern "C" void kernel_launch(void* const* d_in, const int* in_sizes, int n_in,
                              void* d_out, int out_size)
{
    const float* x   = (const float*)d_in[0];
    const float* dct = (const float*)d_in[1];
    float*       out = (float*)d_out;

    dct_blocks_kernel<<<NTHREADS / TPB, TPB>>>(x, dct, out);
}